// round 12
// baseline (speedup 1.0000x reference)
#include <cuda_runtime.h>

#define IMG_H 1536
#define IMG_W 1536
#define NK 8
#define PW 7
#define NR 28      // CLIP_MAX+1 rows of F ever used
#define CLIPM 27

#define BS1 128
#define NCH 4                     // row chunks of 7
#define JB (IMG_W / BS1)          // 12 j-blocks
#define NBLK1 (NK * NCH * JB)     // 384 compute blocks; block NBLK1 = setup
#define NCLS 225                  // max distinct row classes: 1 + 8*28

#define TC 32                     // columns per geneo3 block tile
#define NSPLIT 3                  // class splits (cls mod 3)
#define MAXSPL 75                 // max classes per split = ceil(225/3)
#define NBLK3 ((IMG_W / TC) * NSPLIT)   // 48 * 3 = 144 blocks, ~one per SM
#define NROWS (NK * NR)           // 224
#define NGRP 48                   // class-groups per iteration (384/8)

// Scratch (device globals only — no allocation allowed)
__device__ __align__(16) float g_F[NROWS * IMG_W];  // thresholded F[k][row][j]
__device__ int      g_icount;
// Split-major tap table: g_tap[(split*MAXSPL + m)*32 + t], class = split + 3*m
__device__ __align__(16) int2 g_tap[NSPLIT * MAXSPL * 32];
__device__ unsigned g_enc;             // encoded running max
__device__ unsigned g_done;            // completed geneo3 blocks

// Monotone float <-> uint encoding for atomicMax over signed floats.
__device__ __forceinline__ unsigned enc_f(float f) {
    int b = __float_as_int(f);
    return (b >= 0) ? ((unsigned)b | 0x80000000u) : ~(unsigned)b;
}
__device__ __forceinline__ float dec_f(unsigned u) {
    int b = (u & 0x80000000u) ? (int)(u ^ 0x80000000u) : ~(int)u;
    return __int_as_float(b);
}

// ---------------------------------------------------------------------------
// Kernel A: F[k,row,j] = 1 - (1/49) * sum_{a,b} |P[k,a,b] - pad[a+row, b+j]|
// Thread = (k, j); walks 7 output rows with a 7x7 register rolling window.
// Summation order is EXACTLY the reference's (a-major, b-minor, single chain)
// so F[k,0,0] == thr bitwise and no threshold flips are possible.
// Block NBLK1 = setup: class list + split-major UNMERGED tap table + atomics.
// ---------------------------------------------------------------------------
__global__ void __launch_bounds__(BS1) geneo1_kernel(
        const float* __restrict__ x,
        const float* __restrict__ patterns,
        const float* __restrict__ vectors) {
    const int tid = threadIdx.x;

    if (blockIdx.x == NBLK1) {
        // ---- flag candidate i's, ordered warp-ballot compaction ----
        __shared__ unsigned char flags[IMG_W];
        __shared__ int s_ilist[NCLS];
        __shared__ int s_cnt;
        for (int i = tid; i < IMG_W; i += BS1) flags[i] = 0;
        __syncthreads();
        if (tid == 0) { flags[0] = 1; g_enc = 0u; g_done = 0u; }
        if (tid < NK * NR) {
            const int k = tid / NR, off = tid % NR;
            const int sy = (int)floorf(vectors[2 * k + 1]);
            const int i = sy + 1 + off;
            if (i >= 1 && i < IMG_W) flags[i] = 1;
        }
        __syncthreads();
        if (tid < 32) {
            int base = 0;
            for (int ch = 0; ch < IMG_W / 32; ch++) {
                const int f = flags[ch * 32 + tid];
                const unsigned m = __ballot_sync(0xffffffffu, f);
                if (f) s_ilist[base + __popc(m & ((1u << tid) - 1u))] = ch * 32 + tid;
                base += __popc(m);
            }
            if (tid == 0) { s_cnt = base; g_icount = base; }
        }
        __syncthreads();

        // ---- tap table, split-major: entry e = (class, tap), independent ----
        const int cnt = s_cnt;
        for (int e = tid; e < cnt * 32; e += BS1) {
            const int cls = e >> 5;
            const int t   = e & 31;
            const int i   = s_ilist[cls];
            const int kk  = t >> 2;
            const int c   = t & 3;
            const float v0 = __ldg(&vectors[2 * kk + 0]);
            const float v1 = __ldg(&vectors[2 * kk + 1]);
            const float fx = floorf(v0);
            const float fy = floorf(v1);
            const int   sx = (int)fx;
            const int   sy = (int)fy;
            const float px = fx - v0;
            const float py = fy - v1;
            const int dx = c >> 1;          // corner order matches reference
            const int dy = c & 1;
            const float w = (dx ? (1.0f - px) : px) * (dy ? (1.0f - py) : py);
            int t1 = i - (sy + dy);
            t1 = min(max(t1, 0), CLIPM);
            int r = t1 - (sx + dx);
            r = min(max(r, 0), CLIPM);
            const int split = cls % NSPLIT;
            const int m     = cls / NSPLIT;
            g_tap[(split * MAXSPL + m) * 32 + t] =
                make_int2(kk * NR + r, __float_as_int(w));
        }
        return;
    }

    const int k   = blockIdx.x / (NCH * JB);
    const int rem = blockIdx.x % (NCH * JB);
    const int r0  = (rem / JB) * 7;               // first output row of chunk
    const int j   = (rem % JB) * BS1 + tid;

    // Pattern in registers.
    float p[PW * PW];
    #pragma unroll
    for (int t = 0; t < PW * PW; t++) p[t] = __ldg(&patterns[k * PW * PW + t]);

    // thr = F_raw(0,0): window all zeros there; same sequential order.
    float s = 0.0f;
    #pragma unroll
    for (int t = 0; t < PW * PW; t++) s += fabsf(p[t]);
    const float thr = 1.0f - s * (1.0f / 49.0f);

    // Initial window: x rows r0-7 .. r0-1, cols j-7 .. j-1 (j-7+b).
    float win[PW][PW];
    #pragma unroll
    for (int a = 0; a < PW; a++) {
        const int r = r0 - PW + a;
        #pragma unroll
        for (int b = 0; b < PW; b++) {
            const int c = j - PW + b;
            win[a][b] = (r >= 0 && c >= 0) ? __ldg(&x[r * IMG_W + c]) : 0.0f;
        }
    }

    #pragma unroll
    for (int step = 0; step < PW; step++) {
        const int row = r0 + step;
        float acc = 0.0f;
        #pragma unroll
        for (int a = 0; a < PW; a++)
            #pragma unroll
            for (int b = 0; b < PW; b++)
                acc += fabsf(p[a * PW + b] - win[a][b]);
        const float f = 1.0f - acc * (1.0f / 49.0f);
        g_F[(k * NR + row) * IMG_W + j] = (f > thr) ? f : 0.0f;

        if (step < PW - 1) {
            #pragma unroll
            for (int a = 0; a < PW - 1; a++)
                #pragma unroll
                for (int b = 0; b < PW; b++)
                    win[a][b] = win[a + 1][b];
            #pragma unroll
            for (int b = 0; b < PW; b++) {
                const int c = j - PW + b;           // row 'row' is always >= 0
                win[PW - 1][b] = (c >= 0) ? __ldg(&x[row * IMG_W + c]) : 0.0f;
            }
        }
    }
}

// ---------------------------------------------------------------------------
// Kernel B: 144 blocks = 48 column-tiles x 3 class-splits (~1 per SM).
// Stage BOTH the F tile (224x32, 28KB) and this split's tap slice (19.2KB)
// into smem. Inner loop is pure fixed-latency smem: LDS.64 meta broadcast +
// LDS.128 data + 4 FFMA. No variable-latency op inside the loop.
// ---------------------------------------------------------------------------
__global__ void __launch_bounds__(384) geneo3_kernel(float* __restrict__ out) {
    __shared__ __align__(16) float sF[NROWS * TC];         // 28672 B
    __shared__ __align__(16) int2  sT[MAXSPL * 32];        // 19200 B
    __shared__ float smax[12];
    const int tid   = threadIdx.x;
    const int split = blockIdx.x % NSPLIT;
    const int j0    = (blockIdx.x / NSPLIT) * TC;

    // Stage F tile: 224 rows x 32 cols, float4 granularity.
    for (int e = tid; e < NROWS * (TC / 4); e += 384) {
        const int row = e >> 3;
        const int q   = e & 7;
        ((float4*)sF)[row * (TC / 4) + q] =
            *(const float4*)&g_F[row * IMG_W + j0 + q * 4];
    }
    // Stage tap slice: contiguous 1200 int4 (2400 int2).
    {
        const int4* src = (const int4*)&g_tap[split * MAXSPL * 32];
        for (int e = tid; e < MAXSPL * 32 / 2; e += 384)
            ((int4*)sT)[e] = __ldg(&src[e]);
    }
    __syncthreads();

    const int count = __ldg(&g_icount);
    const int lane8 = tid & 7;                 // col-quad within class
    const int cgrp  = tid >> 3;                // 0..47
    float m = -3.0e38f;

    #pragma unroll
    for (int it = 0; it < 2; it++) {
        const int midx = cgrp + NGRP * it;     // class index within split
        if (split + NSPLIT * midx < count) {
            float4 acc = make_float4(0.f, 0.f, 0.f, 0.f);
            #pragma unroll
            for (int t = 0; t < 32; t++) {
                const int2  mt = sT[midx * 32 + t];
                const float w  = __int_as_float(mt.y);
                const float4 v = ((const float4*)sF)[mt.x * (TC / 4) + lane8];
                acc.x = fmaf(w, v.x, acc.x);
                acc.y = fmaf(w, v.y, acc.y);
                acc.z = fmaf(w, v.z, acc.z);
                acc.w = fmaf(w, v.w, acc.w);
            }
            m = fmaxf(m, fmaxf(fmaxf(acc.x, acc.y), fmaxf(acc.z, acc.w)));
        }
    }

    #pragma unroll
    for (int o = 16; o > 0; o >>= 1)
        m = fmaxf(m, __shfl_xor_sync(0xffffffffu, m, o));
    if ((tid & 31) == 0) smax[tid >> 5] = m;
    __syncthreads();
    if (tid == 0) {
        #pragma unroll
        for (int w = 1; w < 12; w++) m = fmaxf(m, smax[w]);
        atomicMax(&g_enc, enc_f(m));
        __threadfence();
        const unsigned old = atomicAdd(&g_done, 1u);
        if (old == (unsigned)(NBLK3 - 1)) {
            const unsigned u = atomicOr(&g_enc, 0u);   // coherent read
            out[0] = dec_f(u) * (1.0f / 7.0f);
        }
    }
}

extern "C" void kernel_launch(void* const* d_in, const int* in_sizes, int n_in,
                              void* d_out, int out_size) {
    const float* x        = (const float*)d_in[0];
    const float* patterns = (const float*)d_in[1];
    const float* vectors  = (const float*)d_in[2];
    float* out = (float*)d_out;

    geneo1_kernel<<<NBLK1 + 1, BS1>>>(x, patterns, vectors);
    geneo3_kernel<<<NBLK3, 384>>>(out);
}